// round 3
// baseline (speedup 1.0000x reference)
#include <cuda_runtime.h>
#include <math.h>

// ============================================================================
// ConvNorm: DoReFa weight-quantized 3x3 conv + BN (inference) + PACT act quant
// Shapes: x[32,256,56,56], w[256,256,3,3], out[32,256,56,56] fp32
// Implicit GEMM: M = C_out = 256, N = B*H*W = 100352, K = C_in*9 = 2304
// ============================================================================

#define C_IN   256
#define C_OUT  256
#define HH     56
#define WW     56
#define BATCH  32
#define KDIM   (C_IN * 9)          // 2304
#define NDIM   (BATCH * HH * WW)   // 100352
#define HWSZ   (HH * WW)           // 3136

// device scratch (no allocations allowed)
__device__ float g_maxt;
__device__ float g_wpack[KDIM * C_OUT];   // [k][co], k = ci*9+kh*3+kw
__device__ float g_scale[C_OUT];
__device__ float g_bias[C_OUT];

// ---------------------------------------------------------------------------
// XLA / Eigen float32 tanh (bit-exact with jnp.tanh on f32):
// clamp to +-7.90531110763549805, rational poly in x^2, |x|<4e-4 -> x
// ---------------------------------------------------------------------------
__device__ __forceinline__ float xla_tanhf(float x) {
    const float kClamp = 7.90531110763549805f;
    float xc = fminf(fmaxf(x, -kClamp), kClamp);
    float x2 = __fmul_rn(xc, xc);
    float p;
    p = __fmaf_rn(x2, -2.76076847742355e-16f, 2.00018790482477e-13f);
    p = __fmaf_rn(x2, p, -8.60467152213735e-11f);
    p = __fmaf_rn(x2, p,  5.12229709037114e-08f);
    p = __fmaf_rn(x2, p,  1.48572235717979e-05f);
    p = __fmaf_rn(x2, p,  6.37261928875436e-04f);
    p = __fmaf_rn(x2, p,  4.89352455891786e-03f);
    p = __fmul_rn(xc, p);
    float q;
    q = __fmaf_rn(x2, 1.19825839466702e-06f, 1.18534705686654e-04f);
    q = __fmaf_rn(x2, q, 2.26843463243900e-03f);
    q = __fmaf_rn(x2, q, 4.89352518554385e-03f);
    float r = __fdiv_rn(p, q);
    return (fabsf(x) < 0.0004f) ? x : r;
}

// ---------------------------------------------------------------------------
__global__ void k_reset() { g_maxt = 0.0f; }

__global__ void k_maxabs(const float* __restrict__ w, int n) {
    float m = 0.0f;
    for (int i = blockIdx.x * blockDim.x + threadIdx.x; i < n;
         i += gridDim.x * blockDim.x)
        m = fmaxf(m, fabsf(xla_tanhf(w[i])));
    #pragma unroll
    for (int o = 16; o; o >>= 1)
        m = fmaxf(m, __shfl_xor_sync(0xFFFFFFFFu, m, o));
    __shared__ float s[32];
    if ((threadIdx.x & 31) == 0) s[threadIdx.x >> 5] = m;
    __syncthreads();
    if (threadIdx.x < 32) {
        m = (threadIdx.x < (blockDim.x >> 5)) ? s[threadIdx.x] : 0.0f;
        #pragma unroll
        for (int o = 16; o; o >>= 1)
            m = fmaxf(m, __shfl_xor_sync(0xFFFFFFFFu, m, o));
        if (threadIdx.x == 0)
            atomicMax((int*)&g_maxt, __float_as_int(m));  // nonneg floats: int order ok
    }
}

// quantize weights exactly like the reference, pack as [k][co]
__global__ void k_pack(const float* __restrict__ w) {
    int idx = blockIdx.x * blockDim.x + threadIdx.x;
    if (idx >= C_OUT * KDIM) return;
    int co  = idx / KDIM;
    int k   = idx - co * KDIM;        // = ci*9 + kh*3 + kw (matches input layout)
    float t = xla_tanhf(w[idx]);
    t = __fadd_rn(__fdiv_rn(t, __fmul_rn(2.0f, g_maxt)), 0.5f);
    float r  = rintf(__fmul_rn(t, 15.0f));            // round half-to-even, like jnp.round
    float tq = __fdiv_rn(r, 15.0f);
    float wq = __fadd_rn(__fmul_rn(2.0f, tq), -1.0f);
    g_wpack[k * C_OUT + co] = wq;
}

// fold BN into per-channel scale/bias
__global__ void k_chan(const float* __restrict__ gamma, const float* __restrict__ beta,
                       const float* __restrict__ mean,  const float* __restrict__ var) {
    int c = threadIdx.x;
    float inv = __fdiv_rn(gamma[c], __fsqrt_rn(__fadd_rn(var[c], 1e-5f)));
    g_scale[c] = inv;
    g_bias[c]  = __fadd_rn(beta[c], -__fmul_rn(mean[c], inv));
}

// ---------------------------------------------------------------------------
// Main conv: 128x128 block tile, BK=8, 256 threads, 8x8 micro-tile
// ---------------------------------------------------------------------------
#define BM 128
#define BN 128
#define BK 8

__global__ __launch_bounds__(256, 2)
void k_conv(const float* __restrict__ x, float* __restrict__ out,
            const float* __restrict__ alpha_p) {
    __shared__ float As[BK][BM];
    __shared__ float Bs[BK][BN];

    const int tid = threadIdx.x;
    const int m0  = blockIdx.y * BM;
    const int n0  = blockIdx.x * BN;

    // loader: 8 rows (k) x 32 threads, 4 consecutive columns each
    const int lr = tid >> 5;
    const int lc = (tid & 31) << 2;

    // compute: 16x16 thread grid, 8x8 outputs each (split 4+4 with +64 offset)
    const int tx = tid & 15;
    const int ty = tid >> 4;

    float acc[8][8];
    #pragma unroll
    for (int i = 0; i < 8; i++)
        #pragma unroll
        for (int j = 0; j < 8; j++) acc[i][j] = 0.0f;

    // per-thread spatial decode for the 4 N-columns it gathers (k-invariant)
    int bL[4], hL[4], wL[4];
    #pragma unroll
    for (int i = 0; i < 4; i++) {
        int n  = n0 + lc + i;
        int b  = n / HWSZ;
        int hw = n - b * HWSZ;
        int h  = hw / WW;
        bL[i] = b; hL[i] = h; wL[i] = hw - h * WW;
    }

    for (int k0 = 0; k0 < KDIM; k0 += BK) {
        const int k  = k0 + lr;
        // A: packed quantized weights (contiguous in m)
        float4 av = *(const float4*)(&g_wpack[k * C_OUT + m0 + lc]);
        // B: gathered shifted input (zero-padded halo)
        int ci = k / 9;
        int r9 = k - ci * 9;
        int kh = r9 / 3;
        int kw = r9 - kh * 3;
        float bv[4];
        #pragma unroll
        for (int i = 0; i < 4; i++) {
            int ih = hL[i] + kh - 1;
            int iw = wL[i] + kw - 1;
            bool ok = ((unsigned)ih < (unsigned)HH) && ((unsigned)iw < (unsigned)WW);
            bv[i] = ok ? __ldg(&x[((bL[i] * C_IN + ci) * HH + ih) * WW + iw]) : 0.0f;
        }

        __syncthreads();
        *(float4*)(&As[lr][lc]) = av;
        *(float4*)(&Bs[lr][lc]) = make_float4(bv[0], bv[1], bv[2], bv[3]);
        __syncthreads();

        #pragma unroll
        for (int kk = 0; kk < BK; kk++) {
            float a[8], bb[8];
            *(float4*)(a)      = *(const float4*)(&As[kk][ty * 4]);
            *(float4*)(a + 4)  = *(const float4*)(&As[kk][64 + ty * 4]);
            *(float4*)(bb)     = *(const float4*)(&Bs[kk][tx * 4]);
            *(float4*)(bb + 4) = *(const float4*)(&Bs[kk][64 + tx * 4]);
            #pragma unroll
            for (int i = 0; i < 8; i++)
                #pragma unroll
                for (int j = 0; j < 8; j++)
                    acc[i][j] = __fmaf_rn(a[i], bb[j], acc[i][j]);
        }
    }

    // epilogue: BN fold + PACT quant (IEEE div to match reference bit-wise)
    const float a_val    = alpha_p[0];
    const float a_over_n = __fdiv_rn(a_val, 15.0f);
    #pragma unroll
    for (int i = 0; i < 8; i++) {
        int m  = m0 + ((i < 4) ? (ty * 4 + i) : (64 + ty * 4 + (i - 4)));
        float sc = g_scale[m];
        float bi = g_bias[m];
        #pragma unroll
        for (int j = 0; j < 8; j++) {
            int n  = n0 + ((j < 4) ? (tx * 4 + j) : (64 + tx * 4 + (j - 4)));
            int b  = n / HWSZ;
            int hw = n - b * HWSZ;
            float y = __fmaf_rn(acc[i][j], sc, bi);
            y = fminf(fmaxf(y, 0.0f), a_val);
            float q = rintf(__fdiv_rn(__fmul_rn(y, 15.0f), a_val));
            out[(b * C_OUT + m) * HWSZ + hw] = __fmul_rn(q, a_over_n);
        }
    }
}

// ---------------------------------------------------------------------------
extern "C" void kernel_launch(void* const* d_in, const int* in_sizes, int n_in,
                              void* d_out, int out_size) {
    const float* x      = (const float*)d_in[0];
    const float* weight = (const float*)d_in[1];
    const float* gamma  = (const float*)d_in[2];
    const float* beta   = (const float*)d_in[3];
    const float* rmean  = (const float*)d_in[4];
    const float* rvar   = (const float*)d_in[5];
    const float* alpha  = (const float*)d_in[6];
    float* out = (float*)d_out;

    const int WELEMS = C_OUT * KDIM;  // 589824

    k_reset<<<1, 1>>>();
    k_maxabs<<<256, 256>>>(weight, WELEMS);
    k_pack<<<(WELEMS + 255) / 256, 256>>>(weight);
    k_chan<<<1, C_OUT>>>(gamma, beta, rmean, rvar);

    dim3 grid(NDIM / BN, C_OUT / BM);   // 784 x 2
    k_conv<<<grid, 256>>>(x, out, alpha);
    (void)in_sizes; (void)n_in; (void)out_size;
}

// round 5
// speedup vs baseline: 3.2053x; 3.2053x over previous
#include <cuda_runtime.h>
#include <cuda_bf16.h>
#include <stdint.h>
#include <math.h>

// ============================================================================
// ConvNorm via mma.sync bf16 split-precision implicit GEMM (works on sm_103
// without the 'a' feature set; tcgen05 is ptxas-rejected here).
// Weights quantized to odd ints m in [-15,15] (exact bf16); x = hi + lo bf16
// split; conv = (sum m*(hi+lo)) / 15 folded into BN scale.
// GEMM: M=256 (2 blocks of 128), N=100352 (28 tiles of 112 per image), K=4608.
// ============================================================================

#define C_IN   256
#define C_OUT  256
#define HH     56
#define WW     56
#define BATCH  32
#define HWSZ   3136
#define KD     (C_IN * 9)     // 2304 (ci,tap) pairs
#define NCHUNK 144            // K_eff=4608 / BK=32
#define PITCH  80             // smem row pitch bytes (16*odd -> ldmatrix conflict-free)

__device__ float g_maxt;
__device__ __nv_bfloat16 g_wA[NCHUNK * 2 * 128 * 32];  // [chunk][mb][m][kk]
__device__ float g_scale[C_OUT];
__device__ float g_bias[C_OUT];

// ---------------------------------------------------------------------------
// XLA/Eigen fp32 tanh (bit-exact with jnp.tanh)
// ---------------------------------------------------------------------------
__device__ __forceinline__ float xla_tanhf(float x) {
    const float kClamp = 7.90531110763549805f;
    float xc = fminf(fmaxf(x, -kClamp), kClamp);
    float x2 = __fmul_rn(xc, xc);
    float p;
    p = __fmaf_rn(x2, -2.76076847742355e-16f, 2.00018790482477e-13f);
    p = __fmaf_rn(x2, p, -8.60467152213735e-11f);
    p = __fmaf_rn(x2, p,  5.12229709037114e-08f);
    p = __fmaf_rn(x2, p,  1.48572235717979e-05f);
    p = __fmaf_rn(x2, p,  6.37261928875436e-04f);
    p = __fmaf_rn(x2, p,  4.89352455891786e-03f);
    p = __fmul_rn(xc, p);
    float q;
    q = __fmaf_rn(x2, 1.19825839466702e-06f, 1.18534705686654e-04f);
    q = __fmaf_rn(x2, q, 2.26843463243900e-03f);
    q = __fmaf_rn(x2, q, 4.89352518554385e-03f);
    float r = __fdiv_rn(p, q);
    return (fabsf(x) < 0.0004f) ? x : r;
}

__global__ void k_reset() { g_maxt = 0.0f; }

__global__ void k_maxabs(const float* __restrict__ w, int n) {
    float m = 0.0f;
    for (int i = blockIdx.x * blockDim.x + threadIdx.x; i < n;
         i += gridDim.x * blockDim.x)
        m = fmaxf(m, fabsf(xla_tanhf(w[i])));
    #pragma unroll
    for (int o = 16; o; o >>= 1)
        m = fmaxf(m, __shfl_xor_sync(0xFFFFFFFFu, m, o));
    __shared__ float s[32];
    if ((threadIdx.x & 31) == 0) s[threadIdx.x >> 5] = m;
    __syncthreads();
    if (threadIdx.x < 32) {
        m = (threadIdx.x < (blockDim.x >> 5)) ? s[threadIdx.x] : 0.0f;
        #pragma unroll
        for (int o = 16; o; o >>= 1)
            m = fmaxf(m, __shfl_xor_sync(0xFFFFFFFFu, m, o));
        if (threadIdx.x == 0)
            atomicMax((int*)&g_maxt, __float_as_int(m));  // nonneg floats
    }
}

// quantize -> odd int m (exact bf16); duplicate for hi/lo K positions.
// layout: chunk = (ci*9+tap)/16, kk = ((ci*9+tap)%16)*2 + part
__global__ void k_pack(const float* __restrict__ w) {
    int idx = blockIdx.x * blockDim.x + threadIdx.x;
    if (idx >= C_OUT * KD) return;
    int co = idx / KD;
    int k  = idx - co * KD;
    float tv = xla_tanhf(w[idx]);
    tv = __fadd_rn(__fdiv_rn(tv, __fmul_rn(2.0f, g_maxt)), 0.5f);
    float r = rintf(__fmul_rn(tv, 15.0f));
    float m = __fmaf_rn(2.0f, r, -15.0f);
    __nv_bfloat16 mv = __float2bfloat16(m);
    int chunk = k >> 4, cw = k & 15;
    int mbv = co >> 7, mr = co & 127;
    int base = ((chunk * 2 + mbv) * 128 + mr) * 32 + cw * 2;
    g_wA[base]     = mv;   // hi slot
    g_wA[base + 1] = mv;   // lo slot
}

__global__ void k_chan(const float* __restrict__ gamma, const float* __restrict__ beta,
                       const float* __restrict__ mean,  const float* __restrict__ var) {
    int c = threadIdx.x;
    float inv = __fdiv_rn(gamma[c], __fsqrt_rn(__fadd_rn(var[c], 1e-5f)));
    g_scale[c] = inv;
    g_bias[c]  = __fadd_rn(beta[c], -__fmul_rn(mean[c], inv));
}

// ---------------------------------------------------------------------------
__device__ __forceinline__ uint32_t smem_u32(const void* p) {
    uint32_t a;
    asm("{ .reg .u64 t; cvta.to.shared.u64 t, %1; cvt.u32.u64 %0, t; }"
        : "=r"(a) : "l"(p));
    return a;
}
__device__ __forceinline__ void cp16(uint32_t dst, const void* src) {
    asm volatile("cp.async.cg.shared.global [%0], [%1], 16;"
                 :: "r"(dst), "l"(src) : "memory");
}
__device__ __forceinline__ void ldsm4(uint32_t* r, uint32_t a) {
    asm volatile("ldmatrix.sync.aligned.m8n8.x4.shared.b16 {%0,%1,%2,%3}, [%4];"
                 : "=r"(r[0]), "=r"(r[1]), "=r"(r[2]), "=r"(r[3]) : "r"(a));
}
__device__ __forceinline__ void ldsm2(uint32_t* r, uint32_t a) {
    asm volatile("ldmatrix.sync.aligned.m8n8.x2.shared.b16 {%0,%1}, [%2];"
                 : "=r"(r[0]), "=r"(r[1]) : "r"(a));
}
__device__ __forceinline__ void mma16816(float* d, const uint32_t* a, const uint32_t* b) {
    asm volatile("mma.sync.aligned.m16n8k16.row.col.f32.bf16.bf16.f32 "
                 "{%0,%1,%2,%3}, {%4,%5,%6,%7}, {%8,%9}, {%0,%1,%2,%3};"
                 : "+f"(d[0]), "+f"(d[1]), "+f"(d[2]), "+f"(d[3])
                 : "r"(a[0]), "r"(a[1]), "r"(a[2]), "r"(a[3]),
                   "r"(b[0]), "r"(b[1]));
}

// ---------------------------------------------------------------------------
// Main: grid(896, 2), 256 threads. CTA = 128 co x 112 pixels.
// ---------------------------------------------------------------------------
__global__ __launch_bounds__(256, 2)
void k_conv(const float* __restrict__ x, float* __restrict__ out,
            const float* __restrict__ alpha_p) {
    __shared__ __align__(16) char sA[2][128 * PITCH];   // 2 x 10240
    __shared__ __align__(16) char sB[2][112 * PITCH];   // 2 x 8960

    const int tid = threadIdx.x;
    const int wid = tid >> 5, l = tid & 31;
    const int pt  = blockIdx.x % 28;
    const int b   = blockIdx.x / 28;
    const int mb  = blockIdx.y;

    // --- gather mapping: thread = (citap lane c_lane, pixel lane pl), 7 px each
    const int c_lane = tid >> 4;
    const int pl     = tid & 15;
    int hh[7], ww[7];
    #pragma unroll
    for (int i = 0; i < 7; i++) {
        int p = pt * 112 + pl + 16 * i;
        hh[i] = p / 56;
        ww[i] = p - hh[i] * 56;
    }
    const float* xb = x + (size_t)b * C_IN * HWSZ;

    // --- warp tiling + ldmatrix lane addresses
    const int wm = wid & 3, wn = wid >> 2;
    const uint32_t sAu = smem_u32(sA);
    const uint32_t sBu = smem_u32(sB);
    const uint32_t aoff  = sAu + (wm * 32 + (l & 15)) * PITCH + (l >> 4) * 16;
    const int brow4 = (l & 7) + ((l >= 16) ? 8 : 0);
    const uint32_t boff4 = sBu + (wn * 56 + brow4) * PITCH + ((l >> 3) & 1) * 16;
    const uint32_t boff2 = sBu + (wn * 56 + 48 + (l & 7)) * PITCH + ((l >> 3) & 1) * 16;

    float acc[2][7][4];
    #pragma unroll
    for (int i = 0; i < 2; i++)
        #pragma unroll
        for (int j = 0; j < 7; j++)
            #pragma unroll
            for (int q = 0; q < 4; q++) acc[i][j][q] = 0.0f;

    auto gather = [&](float (&v)[7], int j) {
        int cg  = j * 16 + c_lane;
        int ci  = cg / 9;
        int tap = cg - ci * 9;
        int kh  = tap / 3;
        int kw  = tap - kh * 3;
        const float* base = xb + ci * HWSZ;
        #pragma unroll
        for (int ii = 0; ii < 7; ii++) {
            int ih = hh[ii] + kh - 1, iw = ww[ii] + kw - 1;
            bool ok = ((unsigned)ih < 56u) & ((unsigned)iw < 56u);
            v[ii] = ok ? __ldg(base + ih * 56 + iw) : 0.0f;
        }
    };
    auto cvtsts = [&](const float (&v)[7], int buf) {
        #pragma unroll
        for (int ii = 0; ii < 7; ii++) {
            __nv_bfloat16 h = __float2bfloat16(v[ii]);
            float lf = __fsub_rn(v[ii], __bfloat162float(h));
            __nv_bfloat16 lo = __float2bfloat16(lf);
            uint32_t wv = (uint32_t)__bfloat16_as_ushort(h) |
                          ((uint32_t)__bfloat16_as_ushort(lo) << 16);
            uint32_t ad = sBu + buf * 8960 + (pl + 16 * ii) * PITCH + c_lane * 4;
            asm volatile("st.shared.b32 [%0], %1;" :: "r"(ad), "r"(wv));
        }
    };
    auto loadA = [&](int chunk, int buf) {
        const char* src = (const char*)g_wA + (size_t)(chunk * 2 + mb) * 8192;
        uint32_t dbase = sAu + buf * 10240;
        #pragma unroll
        for (int t2 = 0; t2 < 2; t2++) {
            int off = tid * 16 + t2 * 4096;
            cp16(dbase + (off >> 6) * PITCH + (off & 63), src + off);
        }
    };

    float bpA[7], bpB[7];

    // prologue: iter0 staged directly; bpB = iter1 data; A(0) in flight
    gather(bpA, 0);
    cvtsts(bpA, 0);
    gather(bpB, 1);
    loadA(0, 0);
    asm volatile("cp.async.commit_group;" ::: "memory");

    auto body = [&](int i, int cur, float (&bload)[7], float (&bsts)[7]) {
        asm volatile("cp.async.wait_group 0;" ::: "memory");
        __syncthreads();
        int nxt = cur ^ 1;
        if (i + 1 < NCHUNK) loadA(i + 1, nxt);
        asm volatile("cp.async.commit_group;" ::: "memory");
        if (i + 2 < NCHUNK) gather(bload, i + 2);

        const uint32_t ab = aoff  + cur * 10240;
        const uint32_t b4 = boff4 + cur * 8960;
        const uint32_t b2 = boff2 + cur * 8960;
        #pragma unroll
        for (int ks = 0; ks < 2; ks++) {
            uint32_t kcb = ks * 32;
            uint32_t aT[2][4], bT[7][2];
            ldsm4(aT[0], ab + kcb);
            ldsm4(aT[1], ab + 1280 + kcb);
            #pragma unroll
            for (int ntp = 0; ntp < 3; ntp++) {
                uint32_t t4[4];
                ldsm4(t4, b4 + ntp * 1280 + kcb);
                bT[2 * ntp][0] = t4[0]; bT[2 * ntp][1] = t4[1];
                bT[2 * ntp + 1][0] = t4[2]; bT[2 * ntp + 1][1] = t4[3];
            }
            ldsm2(bT[6], b2 + kcb);
            #pragma unroll
            for (int mt = 0; mt < 2; mt++)
                #pragma unroll
                for (int nt = 0; nt < 7; nt++)
                    mma16816(acc[mt][nt], aT[mt], bT[nt]);
        }
        if (i + 1 < NCHUNK) cvtsts(bsts, nxt);
    };

    for (int i = 0; i < NCHUNK; i += 2) {
        body(i,     0, bpA, bpB);
        body(i + 1, 1, bpB, bpA);
    }

    // --- epilogue: BN fold + PACT quant, float2 stores
    const float av  = alpha_p[0];
    const float aon = __fdiv_rn(av, 15.0f);
    #pragma unroll
    for (int mt = 0; mt < 2; mt++) {
        #pragma unroll
        for (int sub = 0; sub < 2; sub++) {
            int co = mb * 128 + wm * 32 + mt * 16 + (l >> 2) + sub * 8;
            float sc15 = __fdiv_rn(g_scale[co], 15.0f);
            float bi   = g_bias[co];
            float* ob = out + (size_t)(b * C_OUT + co) * HWSZ + pt * 112 + wn * 56;
            #pragma unroll
            for (int nt = 0; nt < 7; nt++) {
                float v0 = acc[mt][nt][sub * 2 + 0];
                float v1 = acc[mt][nt][sub * 2 + 1];
                float y0 = __fmaf_rn(v0, sc15, bi);
                float y1 = __fmaf_rn(v1, sc15, bi);
                y0 = fminf(fmaxf(y0, 0.0f), av);
                y1 = fminf(fmaxf(y1, 0.0f), av);
                float q0 = rintf(__fdiv_rn(__fmul_rn(y0, 15.0f), av));
                float q1 = rintf(__fdiv_rn(__fmul_rn(y1, 15.0f), av));
                float2 o = make_float2(__fmul_rn(q0, aon), __fmul_rn(q1, aon));
                *(float2*)(ob + nt * 8 + 2 * (l & 3)) = o;
            }
        }
    }
}

// ---------------------------------------------------------------------------
extern "C" void kernel_launch(void* const* d_in, const int* in_sizes, int n_in,
                              void* d_out, int out_size) {
    const float* x      = (const float*)d_in[0];
    const float* weight = (const float*)d_in[1];
    const float* gamma  = (const float*)d_in[2];
    const float* beta   = (const float*)d_in[3];
    const float* rmean  = (const float*)d_in[4];
    const float* rvar   = (const float*)d_in[5];
    const float* alpha  = (const float*)d_in[6];
    float* out = (float*)d_out;

    const int WELEMS = C_OUT * KD;

    k_reset<<<1, 1>>>();
    k_maxabs<<<256, 256>>>(weight, WELEMS);
    k_pack<<<(WELEMS + 255) / 256, 256>>>(weight);
    k_chan<<<1, C_OUT>>>(gamma, beta, rmean, rvar);

    dim3 grid(BATCH * 28, 2);
    k_conv<<<grid, 256>>>(x, out, alpha);
    (void)in_sizes; (void)n_in; (void)out_size;
}

// round 7
// speedup vs baseline: 4.3384x; 1.3535x over previous
#include <cuda_runtime.h>
#include <cuda_bf16.h>
#include <stdint.h>
#include <math.h>

// ============================================================================
// ConvNorm via mma.sync bf16 split-precision implicit conv, tap-shift SMEM.
// Weights = odd ints m in [-15,15] (exact bf16); x = hi + lo bf16 split;
// conv = (sum m*(hi+lo))/15 folded into BN scale.
// CTA: 128 c_out (blockIdx.y) x 4 output rows x 56 w (one image).
// K loop: 16 chunks of 16 input channels. Per chunk, B = 6x58 padded pixel
// rows x 16 ch (hi & lo tiles); a conv tap (kh,kw) is a constant ldmatrix
// row offset (kh*58+kw). A = [9 taps][128 co][16 ci] per chunk via cp.async.
// ============================================================================

#define C_IN   256
#define C_OUT  256
#define HH     56
#define WW     56
#define BATCH  32
#define HWSZ   3136
#define KD     (C_IN * 9)

#define PITCH  48                 // bytes/row: 16*3 -> conflict-free ldmatrix
#define ABUF   (9 * 128 * PITCH)  // 55296
#define BHALF  (348 * PITCH)      // 16704 (6*58 pixel rows)
#define BBUF   (2 * BHALF)        // hi + lo
#define OFF_B  (2 * ABUF)
#define SMEMT  (OFF_B + 2 * BBUF) // 177408
#define NLOAD  22                 // ceil(5568/256) gather slots per thread
#define SENT   0xFFFFFFFFu

__device__ float g_maxt;
__device__ __nv_bfloat16 g_wA[16 * 2 * 9 * 128 * 16];  // [chunk][mb][tap][co][ci]
__device__ float g_scale[C_OUT];
__device__ float g_bias[C_OUT];

// ---------------------------------------------------------------------------
__device__ __forceinline__ float xla_tanhf(float x) {
    const float kClamp = 7.90531110763549805f;
    float xc = fminf(fmaxf(x, -kClamp), kClamp);
    float x2 = __fmul_rn(xc, xc);
    float p;
    p = __fmaf_rn(x2, -2.76076847742355e-16f, 2.00018790482477e-13f);
    p = __fmaf_rn(x2, p, -8.60467152213735e-11f);
    p = __fmaf_rn(x2, p,  5.12229709037114e-08f);
    p = __fmaf_rn(x2, p,  1.48572235717979e-05f);
    p = __fmaf_rn(x2, p,  6.37261928875436e-04f);
    p = __fmaf_rn(x2, p,  4.89352455891786e-03f);
    p = __fmul_rn(xc, p);
    float q;
    q = __fmaf_rn(x2, 1.19825839466702e-06f, 1.18534705686654e-04f);
    q = __fmaf_rn(x2, q, 2.26843463243900e-03f);
    q = __fmaf_rn(x2, q, 4.89352518554385e-03f);
    float r = __fdiv_rn(p, q);
    return (fabsf(x) < 0.0004f) ? x : r;
}

__global__ void k_reset() { g_maxt = 0.0f; }

__global__ void k_maxabs(const float* __restrict__ w, int n) {
    float m = 0.0f;
    for (int i = blockIdx.x * blockDim.x + threadIdx.x; i < n;
         i += gridDim.x * blockDim.x)
        m = fmaxf(m, fabsf(xla_tanhf(w[i])));
    #pragma unroll
    for (int o = 16; o; o >>= 1)
        m = fmaxf(m, __shfl_xor_sync(0xFFFFFFFFu, m, o));
    __shared__ float s[32];
    if ((threadIdx.x & 31) == 0) s[threadIdx.x >> 5] = m;
    __syncthreads();
    if (threadIdx.x < 32) {
        m = (threadIdx.x < (blockDim.x >> 5)) ? s[threadIdx.x] : 0.0f;
        #pragma unroll
        for (int o = 16; o; o >>= 1)
            m = fmaxf(m, __shfl_xor_sync(0xFFFFFFFFu, m, o));
        if (threadIdx.x == 0)
            atomicMax((int*)&g_maxt, __float_as_int(m));
    }
}

__global__ void k_pack(const float* __restrict__ w) {
    int idx = blockIdx.x * blockDim.x + threadIdx.x;
    if (idx >= C_OUT * KD) return;
    int co = idx / KD;
    int k  = idx - co * KD;
    int ci = k / 9;
    int tap = k - ci * 9;
    float tv = xla_tanhf(w[idx]);
    tv = __fadd_rn(__fdiv_rn(tv, __fmul_rn(2.0f, g_maxt)), 0.5f);
    float r = rintf(__fmul_rn(tv, 15.0f));
    float m = __fmaf_rn(2.0f, r, -15.0f);
    int chunk = ci >> 4, cw = ci & 15;
    int mb = co >> 7, mr = co & 127;
    g_wA[(((chunk * 2 + mb) * 9 + tap) * 128 + mr) * 16 + cw] = __float2bfloat16(m);
}

__global__ void k_chan(const float* __restrict__ gamma, const float* __restrict__ beta,
                       const float* __restrict__ mean,  const float* __restrict__ var) {
    int c = threadIdx.x;
    float inv = __fdiv_rn(gamma[c], __fsqrt_rn(__fadd_rn(var[c], 1e-5f)));
    g_scale[c] = inv;
    g_bias[c]  = __fadd_rn(beta[c], -__fmul_rn(mean[c], inv));
}

// ---------------------------------------------------------------------------
__device__ __forceinline__ uint32_t smem_u32(const void* p) {
    uint32_t a;
    asm("{ .reg .u64 t; cvta.to.shared.u64 t, %1; cvt.u32.u64 %0, t; }"
        : "=r"(a) : "l"(p));
    return a;
}
__device__ __forceinline__ void cp16(uint32_t dst, const void* src) {
    asm volatile("cp.async.cg.shared.global [%0], [%1], 16;"
                 :: "r"(dst), "l"(src) : "memory");
}
__device__ __forceinline__ void ldsm4(uint32_t* r, uint32_t a) {
    asm volatile("ldmatrix.sync.aligned.m8n8.x4.shared.b16 {%0,%1,%2,%3}, [%4];"
                 : "=r"(r[0]), "=r"(r[1]), "=r"(r[2]), "=r"(r[3]) : "r"(a));
}
__device__ __forceinline__ void ldsm2(uint32_t* r, uint32_t a) {
    asm volatile("ldmatrix.sync.aligned.m8n8.x2.shared.b16 {%0,%1}, [%2];"
                 : "=r"(r[0]), "=r"(r[1]) : "r"(a));
}
__device__ __forceinline__ void mma16816(float* d, const uint32_t* a, const uint32_t* b) {
    asm volatile("mma.sync.aligned.m16n8k16.row.col.f32.bf16.bf16.f32 "
                 "{%0,%1,%2,%3}, {%4,%5,%6,%7}, {%8,%9}, {%0,%1,%2,%3};"
                 : "+f"(d[0]), "+f"(d[1]), "+f"(d[2]), "+f"(d[3])
                 : "r"(a[0]), "r"(a[1]), "r"(a[2]), "r"(a[3]),
                   "r"(b[0]), "r"(b[1]));
}

// ---------------------------------------------------------------------------
// grid(448, 2): x = b*14 + htile, y = mb (co half). 256 threads, 8 warps:
// 2 m-warps (64 co) x 4 n-warps (one output row of 56 each).
// ---------------------------------------------------------------------------
__global__ __launch_bounds__(256, 1)
void k_conv(const float* __restrict__ x, float* __restrict__ out,
            const float* __restrict__ alpha_p) {
    extern __shared__ __align__(16) char smem[];
    const uint32_t sAu = smem_u32(smem);
    const uint32_t sBu = sAu + OFF_B;

    const int tid = threadIdx.x;
    const int wid = tid >> 5, l = tid & 31;
    const int wm = wid & 1, wn = wid >> 1;
    const int b  = blockIdx.x / 14;
    const int h0 = (blockIdx.x % 14) * 4;
    const int mb = blockIdx.y;
    const float* xb = x + (size_t)b * C_IN * HWSZ;

    // ---- precompute gather slots: 5568 = 16ci x 6 rows x 58 w ----
    uint32_t packed[NLOAD];
    #pragma unroll
    for (int j = 0; j < NLOAD; j++) {
        int idx = tid + j * 256;
        if (idx < 5568) {
            int pair = idx / 58;
            int w58  = idx - pair * 58;
            int ci   = pair / 6;
            int hr   = pair - ci * 6;
            int ih   = h0 - 1 + hr;
            int iw   = w58 - 1;
            uint32_t ok = ((unsigned)ih < 56u) & ((unsigned)iw < 56u);
            int poff = ok ? (ci * HWSZ + ih * 56 + iw) : 0;
            int sts  = (hr * 58 + w58) * PITCH + ci * 2;
            packed[j] = ((uint32_t)sts << 17) | (ok << 16) | (uint32_t)poff;
        } else packed[j] = SENT;
    }

    float v[NLOAD];
    auto gather = [&](int chunk) {
        const float* base = xb + chunk * 16 * HWSZ;
        #pragma unroll
        for (int j = 0; j < NLOAD; j++)
            if (packed[j] != SENT)
                v[j] = ((packed[j] >> 16) & 1) ? __ldg(base + (packed[j] & 0xFFFF)) : 0.0f;
    };
    auto cvtsts = [&](int buf) {
        uint32_t bb = sBu + buf * BBUF;
        #pragma unroll
        for (int j = 0; j < NLOAD; j++)
            if (packed[j] != SENT) {
                uint32_t sts = packed[j] >> 17;
                __nv_bfloat16 h = __float2bfloat16(v[j]);
                float lf = __fsub_rn(v[j], __bfloat162float(h));
                __nv_bfloat16 lo = __float2bfloat16(lf);
                unsigned short hu = __bfloat16_as_ushort(h);
                unsigned short lu = __bfloat16_as_ushort(lo);
                asm volatile("st.shared.b16 [%0], %1;" :: "r"(bb + sts), "h"(hu));
                asm volatile("st.shared.b16 [%0], %1;" :: "r"(bb + BHALF + sts), "h"(lu));
            }
    };
    auto loadA = [&](int chunk, int buf) {
        const char* src = (const char*)g_wA + (size_t)(chunk * 2 + mb) * 36864;
        uint32_t db = sAu + buf * ABUF;
        #pragma unroll
        for (int j = 0; j < 9; j++) {
            int idx = tid + j * 256;          // 2304 x 16B
            uint32_t dst = db + (idx >> 1) * PITCH + (idx & 1) * 16;
            cp16(dst, src + idx * 16);
        }
    };

    float acc[4][7][4];
    #pragma unroll
    for (int a = 0; a < 4; a++)
        #pragma unroll
        for (int n = 0; n < 7; n++)
            #pragma unroll
            for (int q = 0; q < 4; q++) acc[a][n][q] = 0.0f;

    // lane address components
    const uint32_t a_lrow = (uint32_t)(l & 15) * PITCH + (l >> 4) * 16;
    const int b_lrow4 = (l & 7) + ((l >= 16) ? 8 : 0);
    const uint32_t b_lbyte = ((l >> 3) & 1) * 16;

    // ---- prologue ----
    gather(0);
    cvtsts(0);
    loadA(0, 0);
    asm volatile("cp.async.commit_group;" ::: "memory");

    #pragma unroll 1
    for (int chunk = 0; chunk < 16; chunk++) {
        int cur = chunk & 1, nxt = cur ^ 1;
        asm volatile("cp.async.wait_group 0;" ::: "memory");
        __syncthreads();
        if (chunk < 15) {
            loadA(chunk + 1, nxt);
            asm volatile("cp.async.commit_group;" ::: "memory");
            gather(chunk + 1);          // LDG latency hides under MMAs below
        }

        const uint32_t ab = sAu + cur * ABUF;
        const uint32_t bh = sBu + cur * BBUF;
        #pragma unroll
        for (int tap = 0; tap < 9; tap++) {
            const int kh = tap / 3, kw = tap - kh * 3;
            uint32_t aT[4][4];
            #pragma unroll
            for (int mt = 0; mt < 4; mt++)
                ldsm4(aT[mt], ab + (uint32_t)(tap * 128 + wm * 64 + mt * 16) * PITCH + a_lrow);
            const int rbase = (wn + kh) * 58 + kw;
            #pragma unroll
            for (int part = 0; part < 2; part++) {
                const uint32_t breg = bh + part * BHALF;
                uint32_t bT[7][2];
                #pragma unroll
                for (int ntp = 0; ntp < 3; ntp++) {
                    uint32_t t4[4];
                    ldsm4(t4, breg + (uint32_t)(rbase + ntp * 16 + b_lrow4) * PITCH + b_lbyte);
                    bT[2 * ntp][0] = t4[0]; bT[2 * ntp][1] = t4[1];
                    bT[2 * ntp + 1][0] = t4[2]; bT[2 * ntp + 1][1] = t4[3];
                }
                ldsm2(bT[6], breg + (uint32_t)(rbase + 48 + (l & 7)) * PITCH + b_lbyte);
                #pragma unroll
                for (int mt = 0; mt < 4; mt++)
                    #pragma unroll
                    for (int nt = 0; nt < 7; nt++)
                        mma16816(acc[mt][nt], aT[mt], bT[nt]);
            }
        }
        if (chunk < 15) cvtsts(nxt);
    }

    // ---- epilogue: BN fold + PACT quant ----
    const float av  = alpha_p[0];
    const float aon = __fdiv_rn(av, 15.0f);
    #pragma unroll
    for (int mt = 0; mt < 4; mt++) {
        #pragma unroll
        for (int sub = 0; sub < 2; sub++) {
            int co = mb * 128 + wm * 64 + mt * 16 + (l >> 2) + sub * 8;
            float sc15 = __fdiv_rn(g_scale[co], 15.0f);
            float bi   = g_bias[co];
            float* ob = out + (size_t)(b * C_OUT + co) * HWSZ + (h0 + wn) * 56;
            #pragma unroll
            for (int nt = 0; nt < 7; nt++) {
                float y0 = __fmaf_rn(acc[mt][nt][sub * 2 + 0], sc15, bi);
                float y1 = __fmaf_rn(acc[mt][nt][sub * 2 + 1], sc15, bi);
                y0 = fminf(fmaxf(y0, 0.0f), av);
                y1 = fminf(fmaxf(y1, 0.0f), av);
                float q0 = rintf(__fdiv_rn(__fmul_rn(y0, 15.0f), av));
                float q1 = rintf(__fdiv_rn(__fmul_rn(y1, 15.0f), av));
                *(float2*)(ob + nt * 8 + 2 * (l & 3)) =
                    make_float2(__fmul_rn(q0, aon), __fmul_rn(q1, aon));
            }
        }
    }
}

// ---------------------------------------------------------------------------
extern "C" void kernel_launch(void* const* d_in, const int* in_sizes, int n_in,
                              void* d_out, int out_size) {
    const float* x      = (const float*)d_in[0];
    const float* weight = (const float*)d_in[1];
    const float* gamma  = (const float*)d_in[2];
    const float* beta   = (const float*)d_in[3];
    const float* rmean  = (const float*)d_in[4];
    const float* rvar   = (const float*)d_in[5];
    const float* alpha  = (const float*)d_in[6];
    float* out = (float*)d_out;

    const int WELEMS = C_OUT * KD;

    static int smem_set = 0;
    if (!smem_set) {
        cudaFuncSetAttribute(k_conv, cudaFuncAttributeMaxDynamicSharedMemorySize, SMEMT);
        smem_set = 1;
    }

    k_reset<<<1, 1>>>();
    k_maxabs<<<256, 256>>>(weight, WELEMS);
    k_pack<<<(WELEMS + 255) / 256, 256>>>(weight);
    k_chan<<<1, C_OUT>>>(gamma, beta, rmean, rvar);

    dim3 grid(BATCH * 14, 2);
    k_conv<<<grid, 256, SMEMT>>>(x, out, alpha);
    (void)in_sizes; (void)n_in; (void)out_size;
}